// round 2
// baseline (speedup 1.0000x reference)
#include <cuda_runtime.h>
#include <cstdint>

// Inverse 2D Haar DWT, fused elementwise butterfly (matrices folded to constants).
// Inputs: LL, LH, HL, HH : [B=16, C=64, 128, 128] f32. Output: [B, C, 256, 256] f32.
//
// out[2i,   2j]   = 0.5*(LL - LH - HL + HH)
// out[2i,   2j+1] = 0.5*(LL + LH - HL - HH)
// out[2i+1, 2j]   = 0.5*(LL - LH + HL - HH)
// out[2i+1, 2j+1] = 0.5*(LL + LH + HL + HH)
//
// R2 changes vs R1: streaming cache hints (__ldcs/__stcs) since the 537MB
// stream has zero reuse, and 2x work per thread (rows i and i+64) to double
// per-thread MLP (8 outstanding LDG.64).

static constexpr int H_IN  = 128;
static constexpr int W_IN  = 128;
static constexpr int PLANE_IN  = H_IN * W_IN;        // 16384
static constexpr int PLANE_OUT = 4 * PLANE_IN;       // 65536
static constexpr int W_OUT = 2 * W_IN;               // 256

// thread handles one float2 (2 adjacent j) in row i AND row i+64 of one plane
// threads per plane = 64 rows * 64 float2-cols = 4096
static constexpr int THREADS_PER_PLANE = (H_IN / 2) * (W_IN / 2);  // 4096

__device__ __forceinline__ float2 ldcs2(const float* p) {
    float2 v;
    asm volatile("ld.global.cs.v2.f32 {%0,%1}, [%2];"
                 : "=f"(v.x), "=f"(v.y) : "l"(p));
    return v;
}
__device__ __forceinline__ void stcs4(float* p, float4 v) {
    asm volatile("st.global.cs.v4.f32 [%0], {%1,%2,%3,%4};"
                 :: "l"(p), "f"(v.x), "f"(v.y), "f"(v.z), "f"(v.w));
}

__device__ __forceinline__ void butterfly(float2 a, float2 b, float2 c, float2 d,
                                          float4& r0, float4& r1)
{
    r0.x = 0.5f * (a.x - b.x - c.x + d.x);
    r0.y = 0.5f * (a.x + b.x - c.x - d.x);
    r1.x = 0.5f * (a.x - b.x + c.x - d.x);
    r1.y = 0.5f * (a.x + b.x + c.x + d.x);
    r0.z = 0.5f * (a.y - b.y - c.y + d.y);
    r0.w = 0.5f * (a.y + b.y - c.y - d.y);
    r1.z = 0.5f * (a.y - b.y + c.y - d.y);
    r1.w = 0.5f * (a.y + b.y + c.y + d.y);
}

__global__ void __launch_bounds__(256, 8)
idwt_haar_kernel(const float* __restrict__ LL,
                 const float* __restrict__ LH,
                 const float* __restrict__ HL,
                 const float* __restrict__ HH,
                 float* __restrict__ out)
{
    const int64_t gtid = (int64_t)blockIdx.x * blockDim.x + threadIdx.x;

    const int plane = (int)(gtid >> 12);           // / 4096
    const int rem   = (int)(gtid & 4095);
    const int row   = rem >> 6;                    // input row i in [0,64)
    const int col2  = rem & 63;                    // float2 column index

    const int64_t in_off0  = (int64_t)plane * PLANE_IN + row * W_IN + col2 * 2;
    const int64_t in_off1  = in_off0 + 64 * W_IN;                       // row i+64
    const int64_t out_off0 = (int64_t)plane * PLANE_OUT
                           + (int64_t)(2 * row) * W_OUT + col2 * 4;
    const int64_t out_off1 = out_off0 + (int64_t)128 * W_OUT;           // row 2(i+64)

    // Issue all 8 loads up front — independent, MLP=8.
    const float2 a0 = ldcs2(LL + in_off0);
    const float2 b0 = ldcs2(LH + in_off0);
    const float2 c0 = ldcs2(HL + in_off0);
    const float2 d0 = ldcs2(HH + in_off0);
    const float2 a1 = ldcs2(LL + in_off1);
    const float2 b1 = ldcs2(LH + in_off1);
    const float2 c1 = ldcs2(HL + in_off1);
    const float2 d1 = ldcs2(HH + in_off1);

    float4 r0, r1, s0, s1;
    butterfly(a0, b0, c0, d0, r0, r1);
    butterfly(a1, b1, c1, d1, s0, s1);

    stcs4(out + out_off0,         r0);
    stcs4(out + out_off0 + W_OUT, r1);
    stcs4(out + out_off1,         s0);
    stcs4(out + out_off1 + W_OUT, s1);
}

extern "C" void kernel_launch(void* const* d_in, const int* in_sizes, int n_in,
                              void* d_out, int out_size)
{
    const float* LL = (const float*)d_in[0];
    const float* LH = (const float*)d_in[1];
    const float* HL = (const float*)d_in[2];
    const float* HH = (const float*)d_in[3];
    float* out = (float*)d_out;

    const int64_t n_elems  = (int64_t)in_sizes[0];
    const int64_t planes   = n_elems / PLANE_IN;
    const int64_t nthreads = planes * THREADS_PER_PLANE;

    const int block = 256;
    const int grid  = (int)((nthreads + block - 1) / block);

    idwt_haar_kernel<<<grid, block>>>(LL, LH, HL, HH, out);
}